// round 14
// baseline (speedup 1.0000x reference)
#include <cuda_runtime.h>
#include <cfloat>
#include <climits>
#include <math.h>

// Problem constants
#define Bc 4
#define Nc 500
#define Cc 80
#define Tc 28
#define TTc 784
#define Mc 16
#define Hc 800
#define Wc 800
#define EPSc 1e-8f
#define CANDK 10
#define GMW 25          // 784 bits -> 25 words

#define NTHR 512

// Scratch (device globals; no allocation allowed)
__device__ unsigned g_gmb[Bc * Mc * GMW]; // bit-packed binarized gt masks
__device__ float g_gmsum[Bc * Mc];        // per gt mask sums
__device__ float g_inter[Bc * Nc * Mc];   // [bn][m] sum_t ms*gm
__device__ float g_msum[Bc * Nc * Mc];    // [bn][m] sum_t ms
__device__ float g_cost[Bc * Nc * Mc];    // [bn][m] full SimOTA cost
__device__ float g_ious[Bc * Nc * Mc];    // [bn][m] raw IoU (valid-gated)
__device__ int   g_valid[Bc * Nc];        // per-anchor validity
__device__ unsigned g_selmask[Bc * Nc];   // bit m set if gt m selected anchor n
__device__ double g_acc[5];               // cls, l1, giou, mask, n_fg
__device__ unsigned g_done;               // ticket for final write
__device__ unsigned g_bar[4];             // grid barrier counters (coop path)

__device__ __forceinline__ float fsigm(float x) {
    return __fdividef(1.0f, 1.0f + __expf(-x));
}

// Grid barrier — ONLY used under cudaLaunchCooperativeKernel (co-residency
// guaranteed by the launch, which errors instead of hanging otherwise).
__device__ __forceinline__ void gbarrier(unsigned* ctr, unsigned expected) {
    __syncthreads();
    if (threadIdx.x == 0) {
        __threadfence();
        atomicAdd(ctr, 1u);
        while (*(volatile unsigned*)ctr < expected) __nanosleep(32);
        __threadfence();
    }
    __syncthreads();
}

// ============================ shared phase bodies ============================

// crop+binarize -> bitmask. 512 threads, 2 rounds over 784 pixels.
__device__ __forceinline__ void crop_body(int bm, int tid,
                                          const float* __restrict__ gtb,
                                          const float* __restrict__ gmasks,
                                          int* s_cnt) {
    if (tid == 0) *s_cnt = 0;
    __syncthreads();
    float4 gb = ((const float4*)gtb)[bm];
    float x1 = gb.x, y1 = gb.y, x2 = gb.z, y2 = gb.w;
    const float* mask = gmasks + (size_t)bm * Hc * Wc;
    #pragma unroll
    for (int base = 0; base < 1024; base += NTHR) {
        int pix = base + tid;
        float bin = 0.0f;
        if (pix < TTc) {
            int j = pix / Tc;
            int i = pix % Tc;
            float y = y1 + ((j + 0.5f) * (y2 - y1)) / (float)Tc - 0.5f;
            float x = x1 + ((i + 0.5f) * (x2 - x1)) / (float)Tc - 0.5f;
            float y0f = floorf(y), x0f = floorf(x);
            int y0 = (int)y0f, x0 = (int)x0f;
            float fy = y - y0f, fx = x - x0f;
            float v00 = 0.f, v01 = 0.f, v10 = 0.f, v11 = 0.f;
            bool yi0 = (y0 >= 0 && y0 < Hc);
            bool yi1 = (y0 + 1 >= 0 && y0 + 1 < Hc);
            bool xi0 = (x0 >= 0 && x0 < Wc);
            bool xi1 = (x0 + 1 >= 0 && x0 + 1 < Wc);
            if (yi0 && xi0) v00 = __ldg(&mask[(size_t)y0 * Wc + x0]);
            if (yi0 && xi1) v01 = __ldg(&mask[(size_t)y0 * Wc + x0 + 1]);
            if (yi1 && xi0) v10 = __ldg(&mask[(size_t)(y0 + 1) * Wc + x0]);
            if (yi1 && xi1) v11 = __ldg(&mask[(size_t)(y0 + 1) * Wc + x0 + 1]);
            float s = v00 * (1.f - fy) * (1.f - fx) + v01 * (1.f - fy) * fx +
                      v10 * fy * (1.f - fx) + v11 * fy * fx;
            bin = (s >= 0.5f) ? 1.0f : 0.0f;
        }
        unsigned bits = __ballot_sync(0xffffffffu, bin > 0.0f);
        int word = pix >> 5;
        if ((pix & 31) == 0 && word < GMW) {
            g_gmb[bm * GMW + word] = bits;
            if (bits) atomicAdd(s_cnt, __popc(bits));
        }
    }
    __syncthreads();
    if (tid == 0) g_gmsum[bm] = (float)(*s_cnt);
}

// one (anchor,gt) sigmoid mask dot; explicit 7-deep load batching for MLP.
__device__ __forceinline__ void dot_task(int t, int lane,
                                         const float* __restrict__ masks,
                                         const int* __restrict__ gtc) {
    int bn = t >> 4;
    int m = t & 15;
    int b = bn / Nc;
    int c = gtc[b * Mc + m];
    const float4* mp = (const float4*)(masks + ((size_t)bn * Cc + c) * TTc);
    const unsigned* gw = &g_gmb[(b * Mc + m) * GMW];
    int wbase = lane >> 3;
    int shift = (lane & 7) * 4;
    bool tl = (lane < 4);

    // batch ALL loads first: 6 full rounds + tail (lane<4 covers 192..195)
    float4 v0 = __ldcs(&mp[lane]);
    float4 v1 = __ldcs(&mp[lane + 32]);
    float4 v2 = __ldcs(&mp[lane + 64]);
    float4 v3 = __ldcs(&mp[lane + 96]);
    float4 v4 = __ldcs(&mp[lane + 128]);
    float4 v5 = __ldcs(&mp[lane + 160]);
    float4 v6 = tl ? __ldcs(&mp[192 + lane]) : make_float4(0.f, 0.f, 0.f, 0.f);
    unsigned b0 = __ldg(&gw[wbase]);
    unsigned b1 = __ldg(&gw[wbase + 4]);
    unsigned b2 = __ldg(&gw[wbase + 8]);
    unsigned b3 = __ldg(&gw[wbase + 12]);
    unsigned b4 = __ldg(&gw[wbase + 16]);
    unsigned b5 = __ldg(&gw[wbase + 20]);
    unsigned b6 = tl ? __ldg(&gw[24]) : 0u;

    float si = 0.f, ii = 0.f;
    #define DOT_STEP(V, W) do {                                          \
        unsigned nib = ((W) >> shift) & 0xFu;                            \
        float s0 = fsigm((V).x), s1 = fsigm((V).y);                      \
        float s2 = fsigm((V).z), s3 = fsigm((V).w);                      \
        si += s0 + s1 + s2 + s3;                                         \
        ii += ((nib & 1u) ? s0 : 0.f) + ((nib & 2u) ? s1 : 0.f) +        \
              ((nib & 4u) ? s2 : 0.f) + ((nib & 8u) ? s3 : 0.f);         \
    } while (0)
    DOT_STEP(v0, b0);
    DOT_STEP(v1, b1);
    DOT_STEP(v2, b2);
    DOT_STEP(v3, b3);
    DOT_STEP(v4, b4);
    DOT_STEP(v5, b5);
    if (tl) DOT_STEP(v6, b6);
    #undef DOT_STEP

    #pragma unroll
    for (int o = 16; o; o >>= 1) {
        si += __shfl_xor_sync(0xffffffffu, si, o);
        ii += __shfl_xor_sync(0xffffffffu, ii, o);
    }
    if (lane == 0) {
        g_inter[t] = ii;
        g_msum[t] = si;
    }
}

// cost epilogue for one (anchor,gt) entry e = bn*16+m. Caller guarantees all
// 32 lanes of the warp hold consecutive e (16 entries per anchor = half-warp).
__device__ __forceinline__ void cost_entry(int e, int lane,
                                           const float* __restrict__ logits,
                                           const float* __restrict__ boxes,
                                           const int* __restrict__ gtc,
                                           const float* __restrict__ gtb,
                                           const float* __restrict__ img) {
    int bn = e >> 4;
    int m = e & 15;
    int b = bn / Nc;

    float4 bb = ((const float4*)boxes)[bn];
    float bx1 = bb.x, by1 = bb.y, bx2 = bb.z, by2 = bb.w;
    float cx = (bx1 + bx2) * 0.5f, cy = (by1 + by2) * 0.5f;
    float4 gb = ((const float4*)gtb)[b * Mc + m];
    float gx1 = gb.x, gy1 = gb.y, gx2 = gb.z, gy2 = gb.w;

    bool inbox = (cx > gx1) && (cx < gx2) && (cy > gy1) && (cy < gy2);
    float gcx = (gx1 + gx2) * 0.5f, gcy = (gy1 + gy2) * 0.5f;
    float gw = gx2 - gx1, gh = gy2 - gy1;
    bool inctr = (fabsf(cx - gcx) < 0.25f * gw) &&
                 (fabsf(cy - gcy) < 0.25f * gh);
    bool inboth = inbox && inctr;
    unsigned ball = __ballot_sync(0xffffffffu, inbox || inctr);
    bool valid = (lane < 16) ? ((ball & 0xffffu) != 0u) : ((ball >> 16) != 0u);

    int c2 = gtc[b * Mc + m];
    float lo = logits[(size_t)bn * Cc + c2];
    float p = fsigm(lo);
    float neg = -logf((1.0f - p) + EPSc) * 0.75f * p * p;
    float pos = -logf(p + EPSc) * 0.25f * (1.0f - p) * (1.0f - p);
    float clsc = 2.0f * (pos - neg);

    float i0 = img[b * 4 + 0], i1 = img[b * 4 + 1];
    float i2 = img[b * 4 + 2], i3 = img[b * 4 + 3];
    float nx1 = bx1 / i0, ny1 = by1 / i1, nx2 = bx2 / i2, ny2 = by2 / i3;
    float mx1 = gx1 / i0, my1 = gy1 / i1, mx2 = gx2 / i2, my2 = gy2 / i3;

    float l1c = 5.0f * (fabsf(nx1 - mx1) + fabsf(ny1 - my1) +
                        fabsf(nx2 - mx2) + fabsf(ny2 - my2));

    float ltx = fmaxf(nx1, mx1), lty = fmaxf(ny1, my1);
    float rbx = fminf(nx2, mx2), rby = fminf(ny2, my2);
    float iw = fmaxf(rbx - ltx, 0.f), ih = fmaxf(rby - lty, 0.f);
    float inter = iw * ih;
    float a1 = (nx2 - nx1) * (ny2 - ny1);
    float a2 = (mx2 - mx1) * (my2 - my1);
    float uni = a1 + a2 - inter;
    float iou = inter / (uni + EPSc);
    float ex = fmaxf(fmaxf(nx2, mx2) - fminf(nx1, mx1), 0.f);
    float ey = fmaxf(fmaxf(ny2, my2) - fminf(ny1, my1), 0.f);
    float enc = ex * ey;
    float giou = iou - (enc - uni) / (enc + EPSc);
    float giouc = 2.0f * (1.0f - giou);

    float mu = g_msum[e] + g_gmsum[b * Mc + m] + EPSc;
    float maskc = 5.0f * (1.0f - 2.0f * g_inter[e] / mu);

    float cost = clsc + l1c;
    cost = cost + giouc;
    cost = cost + maskc;
    cost = cost + (inboth ? 0.0f : 1e5f);
    cost = cost + (valid ? 0.0f : 1e9f);
    g_cost[e] = cost;

    float rltx = fmaxf(bx1, gx1), rlty = fmaxf(by1, gy1);
    float rrbx = fminf(bx2, gx2), rrby = fminf(by2, gy2);
    float riw = fmaxf(rrbx - rltx, 0.f), rih = fmaxf(rrby - rlty, 0.f);
    float rinter = riw * rih;
    float ra1 = (bx2 - bx1) * (by2 - by1);
    float ra2 = (gx2 - gx1) * (gy2 - gy1);
    float runi = ra1 + ra2 - rinter;
    float riou = rinter / (runi + EPSc);
    g_ious[e] = riou * (valid ? 1.0f : 0.0f);

    if ((lane & 15) == 0) g_valid[bn] = valid ? 1 : 0;
}

__device__ __forceinline__ void match_body(int bm, int lane) {
    int b = bm / Mc;
    int m = bm % Mc;

    float cv[16], iv[16];
    #pragma unroll
    for (int r = 0; r < 16; r++) {
        int i = lane + 32 * r;
        if (i < Nc) {
            cv[r] = g_cost[(b * Nc + i) * Mc + m];
            iv[r] = g_ious[(b * Nc + i) * Mc + m];
        } else {
            cv[r] = FLT_MAX;
            iv[r] = -FLT_MAX;
        }
    }

    float ksum = 0.0f;
    for (int k = 0; k < CANDK; k++) {
        float best = -FLT_MAX; int bi = INT_MAX;
        #pragma unroll
        for (int r = 0; r < 16; r++)
            if (iv[r] > best) { best = iv[r]; bi = lane + 32 * r; }
        #pragma unroll
        for (int o = 16; o; o >>= 1) {
            float ov = __shfl_xor_sync(0xffffffffu, best, o);
            int oi = __shfl_xor_sync(0xffffffffu, bi, o);
            if (ov > best || (ov == best && oi < bi)) { best = ov; bi = oi; }
        }
        ksum += best;
        int rr = bi >> 5, ll = bi & 31;
        #pragma unroll
        for (int r = 0; r < 16; r++)
            if (r == rr && ll == lane) iv[r] = -FLT_MAX;
    }
    int dyn = (int)ksum;
    if (dyn < 1) dyn = 1;
    if (dyn > CANDK) dyn = CANDK;

    for (int k = 0; k < CANDK; k++) {
        float best = FLT_MAX; int bi = INT_MAX;
        #pragma unroll
        for (int r = 0; r < 16; r++)
            if (cv[r] < best) { best = cv[r]; bi = lane + 32 * r; }
        #pragma unroll
        for (int o = 16; o; o >>= 1) {
            float ov = __shfl_xor_sync(0xffffffffu, best, o);
            int oi = __shfl_xor_sync(0xffffffffu, bi, o);
            if (ov < best || (ov == best && oi < bi)) { best = ov; bi = oi; }
        }
        if (lane == 0 && k < dyn) atomicOr(&g_selmask[b * Nc + bi], 1u << m);
        int rr = bi >> 5, ll = bi & 31;
        #pragma unroll
        for (int r = 0; r < 16; r++)
            if (r == rr && ll == lane) cv[r] = FLT_MAX;
    }
}

__device__ __forceinline__ void loss_body(int g, int lane,
                                          const float* __restrict__ logits,
                                          const float* __restrict__ boxes,
                                          const int* __restrict__ gtc,
                                          const float* __restrict__ gtb,
                                          const float* __restrict__ img,
                                          double* sacc) {
    int b = g / Nc;
    unsigned sel = g_selmask[g];
    int valid = g_valid[g];
    int cnt = __popc(sel);
    if (cnt == 0 || !valid) return;

    int matched;
    if (cnt > 1) {
        float v = (lane < Mc) ? g_cost[g * Mc + lane] : FLT_MAX;
        int bi = (lane < Mc) ? lane : INT_MAX;
        #pragma unroll
        for (int o = 16; o; o >>= 1) {
            float ov = __shfl_xor_sync(0xffffffffu, v, o);
            int oi = __shfl_xor_sync(0xffffffffu, bi, o);
            if (ov < v || (ov == v && oi < bi)) { v = ov; bi = oi; }
        }
        matched = bi;
    } else {
        matched = __ffs(sel) - 1;
    }

    int gm_i = b * Mc + matched;
    int tcls = gtc[gm_i];
    float fsum = 0.0f;
    #pragma unroll
    for (int k = 0; k < 3; k++) {
        int c = lane + 32 * k;
        if (c < Cc) {
            float l = logits[(size_t)g * Cc + c];
            float tgt = (c == tcls) ? 1.0f : 0.0f;
            float p = fsigm(l);
            float ce = fmaxf(l, 0.0f) - l * tgt + log1pf(__expf(-fabsf(l)));
            float pt = p * tgt + (1.0f - p) * (1.0f - tgt);
            float om = 1.0f - pt;
            float w = 0.25f * tgt + 0.75f * (1.0f - tgt);
            fsum += ce * om * om * w;
        }
    }
    #pragma unroll
    for (int o = 16; o; o >>= 1) fsum += __shfl_xor_sync(0xffffffffu, fsum, o);

    if (lane == 0) {
        float i0 = img[b * 4 + 0], i1 = img[b * 4 + 1];
        float i2 = img[b * 4 + 2], i3 = img[b * 4 + 3];
        float4 bb = ((const float4*)boxes)[g];
        float nx1 = bb.x / i0, ny1 = bb.y / i1;
        float nx2 = bb.z / i2, ny2 = bb.w / i3;
        float4 gbv = ((const float4*)gtb)[gm_i];
        float mx1 = gbv.x / i0, my1 = gbv.y / i1;
        float mx2 = gbv.z / i2, my2 = gbv.w / i3;

        float l1v = fabsf(nx1 - mx1) + fabsf(ny1 - my1) +
                    fabsf(nx2 - mx2) + fabsf(ny2 - my2);

        float ltx = fmaxf(nx1, mx1), lty = fmaxf(ny1, my1);
        float rbx = fminf(nx2, mx2), rby = fminf(ny2, my2);
        float iw = fmaxf(rbx - ltx, 0.f), ih = fmaxf(rby - lty, 0.f);
        float inter = iw * ih;
        float a1 = (nx2 - nx1) * (ny2 - ny1);
        float a2 = (mx2 - mx1) * (my2 - my1);
        float uni = a1 + a2 - inter;
        float iou = inter / (uni + EPSc);
        float ex = fmaxf(fmaxf(nx2, mx2) - fminf(nx1, mx1), 0.f);
        float ey = fmaxf(fmaxf(ny2, my2) - fminf(ny1, my1), 0.f);
        float enc = ex * ey;
        float giou = iou - (enc - uni) / (enc + EPSc);
        float gv = 1.0f - giou;

        float mi = g_inter[g * Mc + matched];
        float msv = g_msum[g * Mc + matched];
        float mu = msv + g_gmsum[gm_i] + EPSc;
        float mkv = 1.0f - 2.0f * mi / mu;

        atomicAdd(&sacc[0], (double)fsum);
        atomicAdd(&sacc[1], (double)l1v);
        atomicAdd(&sacc[2], (double)gv);
        atomicAdd(&sacc[3], (double)mkv);
        atomicAdd(&sacc[4], 1.0);
    }
}

// ======================= cooperative fused kernel =======================
__global__ void __launch_bounds__(NTHR, 2)
k_all(const float* __restrict__ logits, const float* __restrict__ boxes,
      const float* __restrict__ masks, const int* __restrict__ gtc,
      const float* __restrict__ gtb, const float* __restrict__ gmasks,
      const float* __restrict__ img, float* __restrict__ out) {
    int bid = blockIdx.x;
    unsigned grid = gridDim.x;
    int tid = threadIdx.x;
    int lane = tid & 31;
    int wid = tid >> 5;

    __shared__ int s_cnt;
    __shared__ double sacc[5];

    // Phase 0: housekeeping + crop
    {
        int gtid = bid * NTHR + tid;
        for (int i = gtid; i < Bc * Nc; i += grid * NTHR) g_selmask[i] = 0u;
        if (gtid < 5) g_acc[gtid] = 0.0;
        if (gtid == 5) g_done = 0u;
    }
    if (bid < Bc * Mc) crop_body(bid, tid, gtb, gmasks, &s_cnt);
    gbarrier(&g_bar[0], grid);

    // Phase 1a: streaming dots, one (anchor,gt) task per warp, no syncs
    {
        int nwarps = grid * (NTHR / 32);
        for (int t = bid * (NTHR / 32) + wid; t < Bc * Nc * Mc; t += nwarps)
            dot_task(t, lane, masks, gtc);
    }
    gbarrier(&g_bar[1], grid);

    // Phase 1b: cost epilogue, one entry per thread (32000 entries)
    for (int e = bid * NTHR + tid; e < Bc * Nc * Mc; e += grid * NTHR)
        cost_entry(e, lane, logits, boxes, gtc, gtb, img);
    gbarrier(&g_bar[2], grid);

    // Phase 2: SimOTA match, warp per gt column
    {
        int gw = bid * (NTHR / 32) + wid;
        if (gw < Bc * Mc) match_body(gw, lane);
    }
    gbarrier(&g_bar[3], grid);

    // Phase 3: losses, warp per anchor
    if (tid < 5) sacc[tid] = 0.0;
    __syncthreads();
    for (int g = bid * (NTHR / 32) + wid; g < Bc * Nc; g += grid * (NTHR / 32))
        loss_body(g, lane, logits, boxes, gtc, gtb, img, sacc);
    __syncthreads();
    if (tid < 5) atomicAdd(&g_acc[tid], sacc[tid]);
    __syncthreads();
    if (tid == 0) {
        __threadfence();
        unsigned ticket = atomicAdd(&g_done, 1u);
        if (ticket == grid - 1) {
            __threadfence();
            double nt = g_acc[4];
            out[0] = (float)(2.0 * g_acc[0] / nt);
            out[1] = (float)(5.0 * g_acc[1] / nt);
            out[2] = (float)(2.0 * g_acc[2] / nt);
            out[3] = (float)(5.0 * g_acc[3] / nt);
            g_bar[0] = 0u;
            g_bar[1] = 0u;
            g_bar[2] = 0u;
            g_bar[3] = 0u;
            g_done = 0u;
        }
    }
}

// ======================= fallback split kernels ============
__global__ void __launch_bounds__(NTHR)
k_crop(const float* __restrict__ gtb, const float* __restrict__ gmasks) {
    int bm = blockIdx.x;
    int tid = threadIdx.x;
    {
        int gtid = bm * NTHR + tid;
        for (int i = gtid; i < Bc * Nc; i += Bc * Mc * NTHR) g_selmask[i] = 0u;
        if (gtid < 5) g_acc[gtid] = 0.0;
        if (gtid == 5) g_done = 0u;
    }
    __shared__ int s_cnt;
    crop_body(bm, tid, gtb, gmasks, &s_cnt);
}

__global__ void __launch_bounds__(NTHR)
k_cost(const float* __restrict__ logits, const float* __restrict__ boxes,
       const float* __restrict__ masks, const int* __restrict__ gtc,
       const float* __restrict__ gtb, const float* __restrict__ img) {
    int bn = blockIdx.x;
    int tid = threadIdx.x;
    int lane = tid & 31;
    int m = tid >> 5;
    dot_task(bn * Mc + m, lane, masks, gtc);
    __syncthreads();
    // warp 0 does the 16 cost entries; lanes 16..31 duplicate 0..15 (benign
    // same-value writes) so the full-warp ballot in cost_entry stays valid.
    if (tid < 32)
        cost_entry(bn * Mc + (lane & 15), lane, logits, boxes, gtc, gtb, img);
}

__global__ void __launch_bounds__(32)
k_match() {
    match_body(blockIdx.x, threadIdx.x);
}

__global__ void __launch_bounds__(256)
k_loss(const float* __restrict__ logits, const float* __restrict__ boxes,
       const int* __restrict__ gtc, const float* __restrict__ gtb,
       const float* __restrict__ img, float* __restrict__ out) {
    __shared__ double sacc[5];
    int tid = threadIdx.x;
    if (tid < 5) sacc[tid] = 0.0;
    __syncthreads();
    int g = blockIdx.x * 8 + (tid >> 5);
    if (g < Bc * Nc)
        loss_body(g, tid & 31, logits, boxes, gtc, gtb, img, sacc);
    __syncthreads();
    if (tid < 5) atomicAdd(&g_acc[tid], sacc[tid]);
    __syncthreads();
    if (tid == 0) {
        __threadfence();
        unsigned ticket = atomicAdd(&g_done, 1u);
        if (ticket == gridDim.x - 1) {
            __threadfence();
            double nt = g_acc[4];
            out[0] = (float)(2.0 * g_acc[0] / nt);
            out[1] = (float)(5.0 * g_acc[1] / nt);
            out[2] = (float)(2.0 * g_acc[2] / nt);
            out[3] = (float)(5.0 * g_acc[3] / nt);
        }
    }
}

extern "C" void kernel_launch(void* const* d_in, const int* in_sizes, int n_in,
                              void* d_out, int out_size) {
    const float* pred_logits = (const float*)d_in[0];
    const float* pred_boxes  = (const float*)d_in[1];
    const float* pred_masks  = (const float*)d_in[2];
    const int*   gt_classes  = (const int*)d_in[3];
    const float* gt_boxes    = (const float*)d_in[4];
    const float* gt_masks    = (const float*)d_in[5];
    const float* image_size  = (const float*)d_in[6];
    float* out = (float*)d_out;

    void* args[] = {
        (void*)&pred_logits, (void*)&pred_boxes, (void*)&pred_masks,
        (void*)&gt_classes, (void*)&gt_boxes, (void*)&gt_masks,
        (void*)&image_size, (void*)&out
    };
    // Try 2 CTAs/SM (296), then 1 CTA/SM (148), then the split pipeline.
    cudaError_t err = cudaLaunchCooperativeKernel(
        (void*)k_all, dim3(296), dim3(NTHR), args, 0, (cudaStream_t)0);
    if (err != cudaSuccess) {
        (void)cudaGetLastError();
        err = cudaLaunchCooperativeKernel(
            (void*)k_all, dim3(148), dim3(NTHR), args, 0, (cudaStream_t)0);
    }
    if (err != cudaSuccess) {
        (void)cudaGetLastError();
        k_crop<<<Bc * Mc, NTHR>>>(gt_boxes, gt_masks);
        k_cost<<<Bc * Nc, NTHR>>>(pred_logits, pred_boxes, pred_masks,
                                  gt_classes, gt_boxes, image_size);
        k_match<<<Bc * Mc, 32>>>();
        k_loss<<<(Bc * Nc) / 8, 256>>>(pred_logits, pred_boxes, gt_classes,
                                       gt_boxes, image_size, out);
    }
}

// round 15
// speedup vs baseline: 1.0269x; 1.0269x over previous
#include <cuda_runtime.h>
#include <cfloat>
#include <climits>
#include <math.h>

// Problem constants
#define Bc 4
#define Nc 500
#define Cc 80
#define Tc 28
#define TTc 784
#define Mc 16
#define Hc 800
#define Wc 800
#define EPSc 1e-8f
#define CANDK 10
#define GMW 25          // 784 bits -> 25 words

#define NTHR 512

// Scratch (device globals; no allocation allowed)
__device__ unsigned g_gmb[Bc * Mc * GMW]; // bit-packed binarized gt masks
__device__ float g_gmsum[Bc * Mc];        // per gt mask sums
__device__ float g_inter[Bc * Nc * Mc];   // [bn][m] sum_t ms*gm
__device__ float g_msum[Bc * Nc * Mc];    // [bn][m] sum_t ms
__device__ float g_cost[Bc * Nc * Mc];    // [bn][m] full SimOTA cost
__device__ float g_ious[Bc * Nc * Mc];    // [bn][m] raw IoU (valid-gated)
__device__ int   g_valid[Bc * Nc];        // per-anchor validity
__device__ unsigned g_selmask[Bc * Nc];   // bit m set if gt m selected anchor n
__device__ double g_acc[5];               // cls, l1, giou, mask, n_fg
__device__ unsigned g_done;               // ticket for final write
__device__ unsigned g_bar[4];             // grid barrier counters (coop path)

__device__ __forceinline__ float fsigm(float x) {
    return __fdividef(1.0f, 1.0f + __expf(-x));
}

// Grid barrier — ONLY used under cudaLaunchCooperativeKernel (co-residency
// guaranteed by the launch, which errors instead of hanging otherwise).
__device__ __forceinline__ void gbarrier(unsigned* ctr, unsigned expected) {
    __syncthreads();
    if (threadIdx.x == 0) {
        __threadfence();
        atomicAdd(ctr, 1u);
        while (*(volatile unsigned*)ctr < expected) __nanosleep(32);
        __threadfence();
    }
    __syncthreads();
}

// ============================ shared phase bodies ============================

// crop+binarize -> bitmask. 512 threads, 2 rounds over 784 pixels.
__device__ __forceinline__ void crop_body(int bm, int tid,
                                          const float* __restrict__ gtb,
                                          const float* __restrict__ gmasks,
                                          int* s_cnt) {
    if (tid == 0) *s_cnt = 0;
    __syncthreads();
    float4 gb = ((const float4*)gtb)[bm];
    float x1 = gb.x, y1 = gb.y, x2 = gb.z, y2 = gb.w;
    const float* mask = gmasks + (size_t)bm * Hc * Wc;
    #pragma unroll
    for (int base = 0; base < 1024; base += NTHR) {
        int pix = base + tid;
        float bin = 0.0f;
        if (pix < TTc) {
            int j = pix / Tc;
            int i = pix % Tc;
            float y = y1 + ((j + 0.5f) * (y2 - y1)) / (float)Tc - 0.5f;
            float x = x1 + ((i + 0.5f) * (x2 - x1)) / (float)Tc - 0.5f;
            float y0f = floorf(y), x0f = floorf(x);
            int y0 = (int)y0f, x0 = (int)x0f;
            float fy = y - y0f, fx = x - x0f;
            float v00 = 0.f, v01 = 0.f, v10 = 0.f, v11 = 0.f;
            bool yi0 = (y0 >= 0 && y0 < Hc);
            bool yi1 = (y0 + 1 >= 0 && y0 + 1 < Hc);
            bool xi0 = (x0 >= 0 && x0 < Wc);
            bool xi1 = (x0 + 1 >= 0 && x0 + 1 < Wc);
            if (yi0 && xi0) v00 = __ldg(&mask[(size_t)y0 * Wc + x0]);
            if (yi0 && xi1) v01 = __ldg(&mask[(size_t)y0 * Wc + x0 + 1]);
            if (yi1 && xi0) v10 = __ldg(&mask[(size_t)(y0 + 1) * Wc + x0]);
            if (yi1 && xi1) v11 = __ldg(&mask[(size_t)(y0 + 1) * Wc + x0 + 1]);
            float s = v00 * (1.f - fy) * (1.f - fx) + v01 * (1.f - fy) * fx +
                      v10 * fy * (1.f - fx) + v11 * fy * fx;
            bin = (s >= 0.5f) ? 1.0f : 0.0f;
        }
        unsigned bits = __ballot_sync(0xffffffffu, bin > 0.0f);
        int word = pix >> 5;
        if ((pix & 31) == 0 && word < GMW) {
            g_gmb[bm * GMW + word] = bits;
            if (bits) atomicAdd(s_cnt, __popc(bits));
        }
    }
    __syncthreads();
    if (tid == 0) g_gmsum[bm] = (float)(*s_cnt);
}

// one (anchor,gt) sigmoid mask dot; explicit 7-deep load batching for MLP.
__device__ __forceinline__ void dot_task(int t, int lane,
                                         const float* __restrict__ masks,
                                         const int* __restrict__ gtc) {
    int bn = t >> 4;
    int m = t & 15;
    int b = bn / Nc;
    int c = gtc[b * Mc + m];
    const float4* mp = (const float4*)(masks + ((size_t)bn * Cc + c) * TTc);
    const unsigned* gw = &g_gmb[(b * Mc + m) * GMW];
    int wbase = lane >> 3;
    int shift = (lane & 7) * 4;
    bool tl = (lane < 4);

    // batch ALL loads first: 6 full rounds + tail (lane<4 covers 192..195)
    float4 v0 = __ldcs(&mp[lane]);
    float4 v1 = __ldcs(&mp[lane + 32]);
    float4 v2 = __ldcs(&mp[lane + 64]);
    float4 v3 = __ldcs(&mp[lane + 96]);
    float4 v4 = __ldcs(&mp[lane + 128]);
    float4 v5 = __ldcs(&mp[lane + 160]);
    float4 v6 = tl ? __ldcs(&mp[192 + lane]) : make_float4(0.f, 0.f, 0.f, 0.f);
    unsigned b0 = __ldg(&gw[wbase]);
    unsigned b1 = __ldg(&gw[wbase + 4]);
    unsigned b2 = __ldg(&gw[wbase + 8]);
    unsigned b3 = __ldg(&gw[wbase + 12]);
    unsigned b4 = __ldg(&gw[wbase + 16]);
    unsigned b5 = __ldg(&gw[wbase + 20]);
    unsigned b6 = tl ? __ldg(&gw[24]) : 0u;

    float si = 0.f, ii = 0.f;
    #define DOT_STEP(V, W) do {                                          \
        unsigned nib = ((W) >> shift) & 0xFu;                            \
        float s0 = fsigm((V).x), s1 = fsigm((V).y);                      \
        float s2 = fsigm((V).z), s3 = fsigm((V).w);                      \
        si += s0 + s1 + s2 + s3;                                         \
        ii += ((nib & 1u) ? s0 : 0.f) + ((nib & 2u) ? s1 : 0.f) +        \
              ((nib & 4u) ? s2 : 0.f) + ((nib & 8u) ? s3 : 0.f);         \
    } while (0)
    DOT_STEP(v0, b0);
    DOT_STEP(v1, b1);
    DOT_STEP(v2, b2);
    DOT_STEP(v3, b3);
    DOT_STEP(v4, b4);
    DOT_STEP(v5, b5);
    if (tl) DOT_STEP(v6, b6);
    #undef DOT_STEP

    #pragma unroll
    for (int o = 16; o; o >>= 1) {
        si += __shfl_xor_sync(0xffffffffu, si, o);
        ii += __shfl_xor_sync(0xffffffffu, ii, o);
    }
    if (lane == 0) {
        g_inter[t] = ii;
        g_msum[t] = si;
    }
}

// cost epilogue for one (anchor,gt) entry e = bn*16+m. Caller guarantees all
// 32 lanes of the warp hold consecutive e (16 entries per anchor = half-warp).
__device__ __forceinline__ void cost_entry(int e, int lane,
                                           const float* __restrict__ logits,
                                           const float* __restrict__ boxes,
                                           const int* __restrict__ gtc,
                                           const float* __restrict__ gtb,
                                           const float* __restrict__ img) {
    int bn = e >> 4;
    int m = e & 15;
    int b = bn / Nc;

    float4 bb = ((const float4*)boxes)[bn];
    float bx1 = bb.x, by1 = bb.y, bx2 = bb.z, by2 = bb.w;
    float cx = (bx1 + bx2) * 0.5f, cy = (by1 + by2) * 0.5f;
    float4 gb = ((const float4*)gtb)[b * Mc + m];
    float gx1 = gb.x, gy1 = gb.y, gx2 = gb.z, gy2 = gb.w;

    bool inbox = (cx > gx1) && (cx < gx2) && (cy > gy1) && (cy < gy2);
    float gcx = (gx1 + gx2) * 0.5f, gcy = (gy1 + gy2) * 0.5f;
    float gw = gx2 - gx1, gh = gy2 - gy1;
    bool inctr = (fabsf(cx - gcx) < 0.25f * gw) &&
                 (fabsf(cy - gcy) < 0.25f * gh);
    bool inboth = inbox && inctr;
    unsigned ball = __ballot_sync(0xffffffffu, inbox || inctr);
    bool valid = (lane < 16) ? ((ball & 0xffffu) != 0u) : ((ball >> 16) != 0u);

    int c2 = gtc[b * Mc + m];
    float lo = logits[(size_t)bn * Cc + c2];
    float p = fsigm(lo);
    float neg = -logf((1.0f - p) + EPSc) * 0.75f * p * p;
    float pos = -logf(p + EPSc) * 0.25f * (1.0f - p) * (1.0f - p);
    float clsc = 2.0f * (pos - neg);

    float i0 = img[b * 4 + 0], i1 = img[b * 4 + 1];
    float i2 = img[b * 4 + 2], i3 = img[b * 4 + 3];
    float nx1 = bx1 / i0, ny1 = by1 / i1, nx2 = bx2 / i2, ny2 = by2 / i3;
    float mx1 = gx1 / i0, my1 = gy1 / i1, mx2 = gx2 / i2, my2 = gy2 / i3;

    float l1c = 5.0f * (fabsf(nx1 - mx1) + fabsf(ny1 - my1) +
                        fabsf(nx2 - mx2) + fabsf(ny2 - my2));

    float ltx = fmaxf(nx1, mx1), lty = fmaxf(ny1, my1);
    float rbx = fminf(nx2, mx2), rby = fminf(ny2, my2);
    float iw = fmaxf(rbx - ltx, 0.f), ih = fmaxf(rby - lty, 0.f);
    float inter = iw * ih;
    float a1 = (nx2 - nx1) * (ny2 - ny1);
    float a2 = (mx2 - mx1) * (my2 - my1);
    float uni = a1 + a2 - inter;
    float iou = inter / (uni + EPSc);
    float ex = fmaxf(fmaxf(nx2, mx2) - fminf(nx1, mx1), 0.f);
    float ey = fmaxf(fmaxf(ny2, my2) - fminf(ny1, my1), 0.f);
    float enc = ex * ey;
    float giou = iou - (enc - uni) / (enc + EPSc);
    float giouc = 2.0f * (1.0f - giou);

    float mu = g_msum[e] + g_gmsum[b * Mc + m] + EPSc;
    float maskc = 5.0f * (1.0f - 2.0f * g_inter[e] / mu);

    float cost = clsc + l1c;
    cost = cost + giouc;
    cost = cost + maskc;
    cost = cost + (inboth ? 0.0f : 1e5f);
    cost = cost + (valid ? 0.0f : 1e9f);
    g_cost[e] = cost;

    float rltx = fmaxf(bx1, gx1), rlty = fmaxf(by1, gy1);
    float rrbx = fminf(bx2, gx2), rrby = fminf(by2, gy2);
    float riw = fmaxf(rrbx - rltx, 0.f), rih = fmaxf(rrby - rlty, 0.f);
    float rinter = riw * rih;
    float ra1 = (bx2 - bx1) * (by2 - by1);
    float ra2 = (gx2 - gx1) * (gy2 - gy1);
    float runi = ra1 + ra2 - rinter;
    float riou = rinter / (runi + EPSc);
    g_ious[e] = riou * (valid ? 1.0f : 0.0f);

    if ((lane & 15) == 0) g_valid[bn] = valid ? 1 : 0;
}

__device__ __forceinline__ void match_body(int bm, int lane) {
    int b = bm / Mc;
    int m = bm % Mc;

    float cv[16], iv[16];
    #pragma unroll
    for (int r = 0; r < 16; r++) {
        int i = lane + 32 * r;
        if (i < Nc) {
            cv[r] = g_cost[(b * Nc + i) * Mc + m];
            iv[r] = g_ious[(b * Nc + i) * Mc + m];
        } else {
            cv[r] = FLT_MAX;
            iv[r] = -FLT_MAX;
        }
    }

    float ksum = 0.0f;
    for (int k = 0; k < CANDK; k++) {
        float best = -FLT_MAX; int bi = INT_MAX;
        #pragma unroll
        for (int r = 0; r < 16; r++)
            if (iv[r] > best) { best = iv[r]; bi = lane + 32 * r; }
        #pragma unroll
        for (int o = 16; o; o >>= 1) {
            float ov = __shfl_xor_sync(0xffffffffu, best, o);
            int oi = __shfl_xor_sync(0xffffffffu, bi, o);
            if (ov > best || (ov == best && oi < bi)) { best = ov; bi = oi; }
        }
        ksum += best;
        int rr = bi >> 5, ll = bi & 31;
        #pragma unroll
        for (int r = 0; r < 16; r++)
            if (r == rr && ll == lane) iv[r] = -FLT_MAX;
    }
    int dyn = (int)ksum;
    if (dyn < 1) dyn = 1;
    if (dyn > CANDK) dyn = CANDK;

    for (int k = 0; k < CANDK; k++) {
        float best = FLT_MAX; int bi = INT_MAX;
        #pragma unroll
        for (int r = 0; r < 16; r++)
            if (cv[r] < best) { best = cv[r]; bi = lane + 32 * r; }
        #pragma unroll
        for (int o = 16; o; o >>= 1) {
            float ov = __shfl_xor_sync(0xffffffffu, best, o);
            int oi = __shfl_xor_sync(0xffffffffu, bi, o);
            if (ov < best || (ov == best && oi < bi)) { best = ov; bi = oi; }
        }
        if (lane == 0 && k < dyn) atomicOr(&g_selmask[b * Nc + bi], 1u << m);
        int rr = bi >> 5, ll = bi & 31;
        #pragma unroll
        for (int r = 0; r < 16; r++)
            if (r == rr && ll == lane) cv[r] = FLT_MAX;
    }
}

__device__ __forceinline__ void loss_body(int g, int lane,
                                          const float* __restrict__ logits,
                                          const float* __restrict__ boxes,
                                          const int* __restrict__ gtc,
                                          const float* __restrict__ gtb,
                                          const float* __restrict__ img,
                                          double* sacc) {
    int b = g / Nc;
    unsigned sel = g_selmask[g];
    int valid = g_valid[g];
    int cnt = __popc(sel);
    if (cnt == 0 || !valid) return;

    int matched;
    if (cnt > 1) {
        float v = (lane < Mc) ? g_cost[g * Mc + lane] : FLT_MAX;
        int bi = (lane < Mc) ? lane : INT_MAX;
        #pragma unroll
        for (int o = 16; o; o >>= 1) {
            float ov = __shfl_xor_sync(0xffffffffu, v, o);
            int oi = __shfl_xor_sync(0xffffffffu, bi, o);
            if (ov < v || (ov == v && oi < bi)) { v = ov; bi = oi; }
        }
        matched = bi;
    } else {
        matched = __ffs(sel) - 1;
    }

    int gm_i = b * Mc + matched;
    int tcls = gtc[gm_i];
    float fsum = 0.0f;
    #pragma unroll
    for (int k = 0; k < 3; k++) {
        int c = lane + 32 * k;
        if (c < Cc) {
            float l = logits[(size_t)g * Cc + c];
            float tgt = (c == tcls) ? 1.0f : 0.0f;
            float p = fsigm(l);
            float ce = fmaxf(l, 0.0f) - l * tgt + log1pf(__expf(-fabsf(l)));
            float pt = p * tgt + (1.0f - p) * (1.0f - tgt);
            float om = 1.0f - pt;
            float w = 0.25f * tgt + 0.75f * (1.0f - tgt);
            fsum += ce * om * om * w;
        }
    }
    #pragma unroll
    for (int o = 16; o; o >>= 1) fsum += __shfl_xor_sync(0xffffffffu, fsum, o);

    if (lane == 0) {
        float i0 = img[b * 4 + 0], i1 = img[b * 4 + 1];
        float i2 = img[b * 4 + 2], i3 = img[b * 4 + 3];
        float4 bb = ((const float4*)boxes)[g];
        float nx1 = bb.x / i0, ny1 = bb.y / i1;
        float nx2 = bb.z / i2, ny2 = bb.w / i3;
        float4 gbv = ((const float4*)gtb)[gm_i];
        float mx1 = gbv.x / i0, my1 = gbv.y / i1;
        float mx2 = gbv.z / i2, my2 = gbv.w / i3;

        float l1v = fabsf(nx1 - mx1) + fabsf(ny1 - my1) +
                    fabsf(nx2 - mx2) + fabsf(ny2 - my2);

        float ltx = fmaxf(nx1, mx1), lty = fmaxf(ny1, my1);
        float rbx = fminf(nx2, mx2), rby = fminf(ny2, my2);
        float iw = fmaxf(rbx - ltx, 0.f), ih = fmaxf(rby - lty, 0.f);
        float inter = iw * ih;
        float a1 = (nx2 - nx1) * (ny2 - ny1);
        float a2 = (mx2 - mx1) * (my2 - my1);
        float uni = a1 + a2 - inter;
        float iou = inter / (uni + EPSc);
        float ex = fmaxf(fmaxf(nx2, mx2) - fminf(nx1, mx1), 0.f);
        float ey = fmaxf(fmaxf(ny2, my2) - fminf(ny1, my1), 0.f);
        float enc = ex * ey;
        float giou = iou - (enc - uni) / (enc + EPSc);
        float gv = 1.0f - giou;

        float mi = g_inter[g * Mc + matched];
        float msv = g_msum[g * Mc + matched];
        float mu = msv + g_gmsum[gm_i] + EPSc;
        float mkv = 1.0f - 2.0f * mi / mu;

        atomicAdd(&sacc[0], (double)fsum);
        atomicAdd(&sacc[1], (double)l1v);
        atomicAdd(&sacc[2], (double)gv);
        atomicAdd(&sacc[3], (double)mkv);
        atomicAdd(&sacc[4], 1.0);
    }
}

// ======================= cooperative fused kernel =======================
__global__ void __launch_bounds__(NTHR, 2)
k_all(const float* __restrict__ logits, const float* __restrict__ boxes,
      const float* __restrict__ masks, const int* __restrict__ gtc,
      const float* __restrict__ gtb, const float* __restrict__ gmasks,
      const float* __restrict__ img, float* __restrict__ out) {
    int bid = blockIdx.x;
    unsigned grid = gridDim.x;
    int tid = threadIdx.x;
    int lane = tid & 31;
    int wid = tid >> 5;

    __shared__ int s_cnt;
    __shared__ double sacc[5];

    // Phase 0: housekeeping + crop
    {
        int gtid = bid * NTHR + tid;
        for (int i = gtid; i < Bc * Nc; i += grid * NTHR) g_selmask[i] = 0u;
        if (gtid < 5) g_acc[gtid] = 0.0;
        if (gtid == 5) g_done = 0u;
    }
    if (bid < Bc * Mc) crop_body(bid, tid, gtb, gmasks, &s_cnt);
    gbarrier(&g_bar[0], grid);

    // Phase 1a: streaming dots, one (anchor,gt) task per warp, no syncs
    {
        int nwarps = grid * (NTHR / 32);
        for (int t = bid * (NTHR / 32) + wid; t < Bc * Nc * Mc; t += nwarps)
            dot_task(t, lane, masks, gtc);
    }
    gbarrier(&g_bar[1], grid);

    // Phase 1b: cost epilogue, one entry per thread (32000 entries)
    for (int e = bid * NTHR + tid; e < Bc * Nc * Mc; e += grid * NTHR)
        cost_entry(e, lane, logits, boxes, gtc, gtb, img);
    gbarrier(&g_bar[2], grid);

    // Phase 2: SimOTA match, warp per gt column
    {
        int gw = bid * (NTHR / 32) + wid;
        if (gw < Bc * Mc) match_body(gw, lane);
    }
    gbarrier(&g_bar[3], grid);

    // Phase 3: losses, warp per anchor
    if (tid < 5) sacc[tid] = 0.0;
    __syncthreads();
    for (int g = bid * (NTHR / 32) + wid; g < Bc * Nc; g += grid * (NTHR / 32))
        loss_body(g, lane, logits, boxes, gtc, gtb, img, sacc);
    __syncthreads();
    if (tid < 5) atomicAdd(&g_acc[tid], sacc[tid]);
    __syncthreads();
    if (tid == 0) {
        __threadfence();
        unsigned ticket = atomicAdd(&g_done, 1u);
        if (ticket == grid - 1) {
            __threadfence();
            double nt = g_acc[4];
            out[0] = (float)(2.0 * g_acc[0] / nt);
            out[1] = (float)(5.0 * g_acc[1] / nt);
            out[2] = (float)(2.0 * g_acc[2] / nt);
            out[3] = (float)(5.0 * g_acc[3] / nt);
            g_bar[0] = 0u;
            g_bar[1] = 0u;
            g_bar[2] = 0u;
            g_bar[3] = 0u;
            g_done = 0u;
        }
    }
}

// ======================= fallback split kernels ============
__global__ void __launch_bounds__(NTHR)
k_crop(const float* __restrict__ gtb, const float* __restrict__ gmasks) {
    int bm = blockIdx.x;
    int tid = threadIdx.x;
    {
        int gtid = bm * NTHR + tid;
        for (int i = gtid; i < Bc * Nc; i += Bc * Mc * NTHR) g_selmask[i] = 0u;
        if (gtid < 5) g_acc[gtid] = 0.0;
        if (gtid == 5) g_done = 0u;
    }
    __shared__ int s_cnt;
    crop_body(bm, tid, gtb, gmasks, &s_cnt);
}

__global__ void __launch_bounds__(NTHR)
k_cost(const float* __restrict__ logits, const float* __restrict__ boxes,
       const float* __restrict__ masks, const int* __restrict__ gtc,
       const float* __restrict__ gtb, const float* __restrict__ img) {
    int bn = blockIdx.x;
    int tid = threadIdx.x;
    int lane = tid & 31;
    int m = tid >> 5;
    dot_task(bn * Mc + m, lane, masks, gtc);
    __syncthreads();
    // warp 0 does the 16 cost entries; lanes 16..31 duplicate 0..15 (benign
    // same-value writes) so the full-warp ballot in cost_entry stays valid.
    if (tid < 32)
        cost_entry(bn * Mc + (lane & 15), lane, logits, boxes, gtc, gtb, img);
}

__global__ void __launch_bounds__(32)
k_match() {
    match_body(blockIdx.x, threadIdx.x);
}

__global__ void __launch_bounds__(256)
k_loss(const float* __restrict__ logits, const float* __restrict__ boxes,
       const int* __restrict__ gtc, const float* __restrict__ gtb,
       const float* __restrict__ img, float* __restrict__ out) {
    __shared__ double sacc[5];
    int tid = threadIdx.x;
    if (tid < 5) sacc[tid] = 0.0;
    __syncthreads();
    int g = blockIdx.x * 8 + (tid >> 5);
    if (g < Bc * Nc)
        loss_body(g, tid & 31, logits, boxes, gtc, gtb, img, sacc);
    __syncthreads();
    if (tid < 5) atomicAdd(&g_acc[tid], sacc[tid]);
    __syncthreads();
    if (tid == 0) {
        __threadfence();
        unsigned ticket = atomicAdd(&g_done, 1u);
        if (ticket == gridDim.x - 1) {
            __threadfence();
            double nt = g_acc[4];
            out[0] = (float)(2.0 * g_acc[0] / nt);
            out[1] = (float)(5.0 * g_acc[1] / nt);
            out[2] = (float)(2.0 * g_acc[2] / nt);
            out[3] = (float)(5.0 * g_acc[3] / nt);
        }
    }
}

extern "C" void kernel_launch(void* const* d_in, const int* in_sizes, int n_in,
                              void* d_out, int out_size) {
    const float* pred_logits = (const float*)d_in[0];
    const float* pred_boxes  = (const float*)d_in[1];
    const float* pred_masks  = (const float*)d_in[2];
    const int*   gt_classes  = (const int*)d_in[3];
    const float* gt_boxes    = (const float*)d_in[4];
    const float* gt_masks    = (const float*)d_in[5];
    const float* image_size  = (const float*)d_in[6];
    float* out = (float*)d_out;

    void* args[] = {
        (void*)&pred_logits, (void*)&pred_boxes, (void*)&pred_masks,
        (void*)&gt_classes, (void*)&gt_boxes, (void*)&gt_masks,
        (void*)&image_size, (void*)&out
    };
    // Try 2 CTAs/SM (296), then 1 CTA/SM (148), then the split pipeline.
    cudaError_t err = cudaLaunchCooperativeKernel(
        (void*)k_all, dim3(296), dim3(NTHR), args, 0, (cudaStream_t)0);
    if (err != cudaSuccess) {
        (void)cudaGetLastError();
        err = cudaLaunchCooperativeKernel(
            (void*)k_all, dim3(148), dim3(NTHR), args, 0, (cudaStream_t)0);
    }
    if (err != cudaSuccess) {
        (void)cudaGetLastError();
        k_crop<<<Bc * Mc, NTHR>>>(gt_boxes, gt_masks);
        k_cost<<<Bc * Nc, NTHR>>>(pred_logits, pred_boxes, pred_masks,
                                  gt_classes, gt_boxes, image_size);
        k_match<<<Bc * Mc, 32>>>();
        k_loss<<<(Bc * Nc) / 8, 256>>>(pred_logits, pred_boxes, gt_classes,
                                       gt_boxes, image_size, out);
    }
}